// round 16
// baseline (speedup 1.0000x reference)
#include <cuda_runtime.h>
#include <cuda_bf16.h>
#include <cstdint>

// ---------------------------------------------------------------------------
// Problem constants
// ---------------------------------------------------------------------------
#define NPF 20000
#define NGW 100000
#define NSW 30000
#define D   128

#define EPG 1600000
#define EGP 640000
#define EPS 480000
#define ESP 320000
#define ETOT (EPG + EGP + EPS + ESP)

#define NTOT (NGW + NPF + NSW + NPF)

// ---------------------------------------------------------------------------
// Device scratch (no allocations allowed -> __device__ globals)
// ---------------------------------------------------------------------------
__device__ float g_mean_gw[(size_t)NGW * D];
__device__ float g_mean_sw[(size_t)NSW * D];
__device__ float g_mean_gp[(size_t)NPF * D];
__device__ float g_mean_sp[(size_t)NPF * D];
__device__ int   g_cnt[NTOT];
__device__ int   g_rowptr[NTOT];
__device__ int   g_cursor[NTOT];
__device__ int   g_perm[ETOT];
__device__ int   g_partials[4 * 128];
__device__ float g_wr_comb[D * D];

// ---------------------------------------------------------------------------
// small utility kernels
// ---------------------------------------------------------------------------
__global__ void zero_int_kernel(int* __restrict__ p, int n4) {
    int i = blockIdx.x * blockDim.x + threadIdx.x;
    if (i < n4) reinterpret_cast<int4*>(p)[i] = make_int4(0, 0, 0, 0);
}

__global__ void addw_kernel(const float* __restrict__ a, const float* __restrict__ b,
                            float* __restrict__ o) {
    int i = blockIdx.x * blockDim.x + threadIdx.x;
    if (i < D * D) o[i] = a[i] + b[i];
}

// ---------------------------------------------------------------------------
// CSR build: histogram -> scan -> permutation (per relation)
// ---------------------------------------------------------------------------
__global__ void hist_kernel(const int* __restrict__ dst, int* __restrict__ cnt, int E) {
    int e = blockIdx.x * blockDim.x + threadIdx.x;
    if (e < E) atomicAdd(&cnt[dst[e]], 1);
}

__global__ void scan_reduce_kernel(const int* __restrict__ cnt, int n,
                                   int* __restrict__ partials) {
    __shared__ int s[256];
    int t = threadIdx.x;
    int base = blockIdx.x * 1024 + t * 4;
    int sum = 0;
#pragma unroll
    for (int j = 0; j < 4; j++) {
        int idx = base + j;
        if (idx < n) sum += cnt[idx];
    }
    s[t] = sum;
    __syncthreads();
    for (int off = 128; off > 0; off >>= 1) {
        if (t < off) s[t] += s[t + off];
        __syncthreads();
    }
    if (t == 0) partials[blockIdx.x] = s[0];
}

// parallel exclusive scan of <=128 partials
__global__ void scan_partials_kernel(int* __restrict__ partials, int nb) {
    __shared__ int s[128];
    int t = threadIdx.x;
    int v = (t < nb) ? partials[t] : 0;
    s[t] = v;
    __syncthreads();
    for (int off = 1; off < 128; off <<= 1) {
        int y = (t >= off) ? s[t - off] : 0;
        __syncthreads();
        s[t] += y;
        __syncthreads();
    }
    if (t < nb) partials[t] = s[t] - v;
}

__global__ void scan_write_kernel(const int* __restrict__ cnt, int n,
                                  const int* __restrict__ partials,
                                  int* __restrict__ rowptr,
                                  int* __restrict__ cursor) {
    __shared__ int wsum[8];
    __shared__ int woff[8];
    int t = threadIdx.x;
    int lane = t & 31, warp = t >> 5;
    int base = blockIdx.x * 1024 + t * 4;
    int v[4];
    int tsum = 0;
#pragma unroll
    for (int j = 0; j < 4; j++) {
        int idx = base + j;
        v[j] = (idx < n) ? cnt[idx] : 0;
        tsum += v[j];
    }
    int incl = tsum;
#pragma unroll
    for (int o = 1; o < 32; o <<= 1) {
        int y = __shfl_up_sync(0xffffffffu, incl, o);
        if (lane >= o) incl += y;
    }
    int excl = incl - tsum;
    if (lane == 31) wsum[warp] = incl;
    __syncthreads();
    if (t == 0) {
        int r = 0;
        for (int i = 0; i < 8; i++) { woff[i] = r; r += wsum[i]; }
    }
    __syncthreads();
    int run = partials[blockIdx.x] + woff[warp] + excl;
#pragma unroll
    for (int j = 0; j < 4; j++) {
        int idx = base + j;
        if (idx < n) { rowptr[idx] = run; cursor[idx] = run; run += v[j]; }
    }
}

__global__ void permute_kernel(const int* __restrict__ src, const int* __restrict__ dst,
                               int* __restrict__ cursor, int* __restrict__ perm, int E) {
    int e = blockIdx.x * blockDim.x + threadIdx.x;
    if (e < E) {
        int pos = atomicAdd(&cursor[dst[e]], 1);
        perm[pos] = src[e];
    }
}

// ---------------------------------------------------------------------------
// Pull aggregation (fp32): one warp per destination node, 8-edge batching
// for higher MLP (gather is latency/issue-bound per R14 evidence).
// ---------------------------------------------------------------------------
__global__ __launch_bounds__(256) void aggregate_kernel(
    const float* __restrict__ x,
    const int*   __restrict__ rowptr,
    const int*   __restrict__ perm,
    float* __restrict__ outmean,
    int N, int E)
{
    int w = (blockIdx.x * blockDim.x + threadIdx.x) >> 5;
    int lane = threadIdx.x & 31;
    if (w >= N) return;

    int start = rowptr[w];
    int end   = (w + 1 < N) ? rowptr[w + 1] : E;

    float4 acc = make_float4(0.f, 0.f, 0.f, 0.f);
    for (int e0 = start; e0 < end; e0 += 32) {
        int idx = (e0 + lane < end) ? perm[e0 + lane] : 0;
        int m = min(32, end - e0);
        int j = 0;
        for (; j + 8 <= m; j += 8) {
            float4 v[8];
#pragma unroll
            for (int q = 0; q < 8; q++) {
                int s = __shfl_sync(0xffffffffu, idx, j + q);
                v[q] = *reinterpret_cast<const float4*>(x + (size_t)s * D + lane * 4);
            }
#pragma unroll
            for (int q = 0; q < 8; q++) {
                acc.x += v[q].x; acc.y += v[q].y; acc.z += v[q].z; acc.w += v[q].w;
            }
        }
        for (; j < m; j++) {
            int s = __shfl_sync(0xffffffffu, idx, j);
            float4 v = *reinterpret_cast<const float4*>(x + (size_t)s * D + lane * 4);
            acc.x += v.x; acc.y += v.y; acc.z += v.z; acc.w += v.w;
        }
    }
    float inv = 1.0f / fmaxf((float)(end - start), 1.0f);
    acc.x *= inv; acc.y *= inv; acc.z *= inv; acc.w *= inv;
    *reinterpret_cast<float4*>(outmean + (size_t)w * D + lane * 4) = acc;
}

// ---------------------------------------------------------------------------
// Fused GEMM, f32x2 packed, double-buffered (R15 proven):
//   h[row, :] = sum_seg A_seg[row, :] @ W_seg + bias1 (+ bias2)
//   MODE 0: out[row*128 + c] = relu(h)
//   MODE 1: out[row] = relu(h) . whead + bhead
// ---------------------------------------------------------------------------
template<int NSEG, int MODE>
__global__ __launch_bounds__(256) void gemm_fused(
    const float* __restrict__ A0, const float* __restrict__ A1,
    const float* __restrict__ A2,
    const float* __restrict__ W0, const float* __restrict__ W1,
    const float* __restrict__ W2,
    const float* __restrict__ bias1, const float* __restrict__ bias2,
    const float* __restrict__ whead, const float* __restrict__ bhead,
    float* __restrict__ out, int n_rows)
{
    constexpr int KC  = 16;
    constexpr int LDT = 132;
    __shared__ float As[2][KC][LDT];
    __shared__ float Ws[2][KC][LDT];
    __shared__ float red[128];

    const int t    = threadIdx.x;
    const int row0 = blockIdx.x * 128;
    const int trow = t >> 4;
    const int tcol = t & 15;

    const float* Aseg[3] = {A0, A1, A2};
    const float* Wseg[3] = {W0, W1, W2};

    const int a_row = t >> 1;
    const int a_q   = (t & 1) * 2;
    const int w_kk  = t >> 4;
    const int w_cq  = t & 15;

    unsigned long long accp[8][4];
#pragma unroll
    for (int i = 0; i < 8; i++)
#pragma unroll
        for (int j2 = 0; j2 < 4; j2++) accp[i][j2] = 0ull;

    const int nchunks = NSEG * D / KC;

    float4 pa0, pa1, pw0, pw1;

    auto prefetch = [&](int ch) {
        const int k0   = ch * KC;
        const int seg  = k0 / D;
        const int kin0 = k0 % D;
        const float* A = Aseg[seg];
        const float* W = Wseg[seg];
        int grow = row0 + a_row;
        if (grow < n_rows) {
            pa0 = *reinterpret_cast<const float4*>(A + (size_t)grow * D + kin0 + a_q * 4);
            pa1 = *reinterpret_cast<const float4*>(A + (size_t)grow * D + kin0 + (a_q + 1) * 4);
        } else {
            pa0 = make_float4(0.f, 0.f, 0.f, 0.f);
            pa1 = make_float4(0.f, 0.f, 0.f, 0.f);
        }
        pw0 = *reinterpret_cast<const float4*>(W + (size_t)(kin0 + w_kk) * D + w_cq * 4);
        pw1 = *reinterpret_cast<const float4*>(W + (size_t)(kin0 + w_kk) * D + (w_cq + 16) * 4);
    };

    auto store_stage = [&](int b) {
        As[b][a_q * 4 + 0][a_row] = pa0.x;
        As[b][a_q * 4 + 1][a_row] = pa0.y;
        As[b][a_q * 4 + 2][a_row] = pa0.z;
        As[b][a_q * 4 + 3][a_row] = pa0.w;
        As[b][a_q * 4 + 4][a_row] = pa1.x;
        As[b][a_q * 4 + 5][a_row] = pa1.y;
        As[b][a_q * 4 + 6][a_row] = pa1.z;
        As[b][a_q * 4 + 7][a_row] = pa1.w;
        *reinterpret_cast<float4*>(&Ws[b][w_kk][w_cq * 4]) = pw0;
        *reinterpret_cast<float4*>(&Ws[b][w_kk][(w_cq + 16) * 4]) = pw1;
    };

    prefetch(0);

    for (int ch = 0; ch < nchunks; ch++) {
        const int b = ch & 1;
        store_stage(b);
        __syncthreads();
        if (ch + 1 < nchunks) prefetch(ch + 1);

#pragma unroll
        for (int kk = 0; kk < KC; kk++) {
            float4 a0 = *reinterpret_cast<const float4*>(&As[b][kk][trow * 4]);
            float4 a1 = *reinterpret_cast<const float4*>(&As[b][kk][64 + trow * 4]);
            unsigned long long wp[4];
            wp[0] = *reinterpret_cast<const unsigned long long*>(&Ws[b][kk][tcol * 4]);
            wp[1] = *reinterpret_cast<const unsigned long long*>(&Ws[b][kk][tcol * 4 + 2]);
            wp[2] = *reinterpret_cast<const unsigned long long*>(&Ws[b][kk][64 + tcol * 4]);
            wp[3] = *reinterpret_cast<const unsigned long long*>(&Ws[b][kk][64 + tcol * 4 + 2]);
            float a[8] = {a0.x, a0.y, a0.z, a0.w, a1.x, a1.y, a1.z, a1.w};
#pragma unroll
            for (int i = 0; i < 8; i++) {
                unsigned long long ap;
                asm("mov.b64 %0, {%1, %1};" : "=l"(ap) : "f"(a[i]));
#pragma unroll
                for (int j2 = 0; j2 < 4; j2++)
                    asm("fma.rn.f32x2 %0, %1, %2, %0;"
                        : "+l"(accp[i][j2]) : "l"(ap), "l"(wp[j2]));
            }
        }
    }

    float acc[8][8];
#pragma unroll
    for (int i = 0; i < 8; i++)
#pragma unroll
        for (int j2 = 0; j2 < 4; j2++)
            asm("mov.b64 {%0, %1}, %2;"
                : "=f"(acc[i][2 * j2]), "=f"(acc[i][2 * j2 + 1]) : "l"(accp[i][j2]));

    int cidx[8], ridx[8];
#pragma unroll
    for (int j = 0; j < 8; j++)
        cidx[j] = (j < 4) ? (tcol * 4 + j) : (64 + tcol * 4 + (j - 4));
#pragma unroll
    for (int i = 0; i < 8; i++)
        ridx[i] = (i < 4) ? (trow * 4 + i) : (64 + trow * 4 + (i - 4));

    float b[8];
#pragma unroll
    for (int j = 0; j < 8; j++)
        b[j] = bias1[cidx[j]] + (bias2 ? bias2[cidx[j]] : 0.f);

    if (MODE == 0) {
#pragma unroll
        for (int i = 0; i < 8; i++) {
            int grow = row0 + ridx[i];
            if (grow < n_rows) {
#pragma unroll
                for (int j = 0; j < 8; j++)
                    out[(size_t)grow * D + cidx[j]] = fmaxf(acc[i][j] + b[j], 0.f);
            }
        }
    } else {
        float wh[8];
#pragma unroll
        for (int j = 0; j < 8; j++) wh[j] = whead[cidx[j]];
        __syncthreads();
        if (t < 128) red[t] = 0.f;
        __syncthreads();
#pragma unroll
        for (int i = 0; i < 8; i++) {
            float partial = 0.f;
#pragma unroll
            for (int j = 0; j < 8; j++)
                partial += fmaxf(acc[i][j] + b[j], 0.f) * wh[j];
            atomicAdd(&red[ridx[i]], partial);
        }
        __syncthreads();
        if (t < 128) {
            int grow = row0 + t;
            if (grow < n_rows) out[grow] = red[t] + bhead[0];
        }
    }
}

// ---------------------------------------------------------------------------
// Launch: 3-branch fork (2 streams + 4 events), pfas gemm rebalanced onto s2.
// ---------------------------------------------------------------------------
extern "C" void kernel_launch(void* const* d_in, const int* in_sizes, int n_in,
                              void* d_out, int out_size)
{
    const float* x_pfas = (const float*)d_in[0];
    const float* x_gw   = (const float*)d_in[1];
    const float* x_sw   = (const float*)d_in[2];
    const int* ei_pg_src = (const int*)d_in[3];
    const int* ei_pg_dst = (const int*)d_in[4];
    const int* ei_gp_src = (const int*)d_in[5];
    const int* ei_gp_dst = (const int*)d_in[6];
    const int* ei_ps_src = (const int*)d_in[7];
    const int* ei_ps_dst = (const int*)d_in[8];
    const int* ei_sp_src = (const int*)d_in[9];
    const int* ei_sp_dst = (const int*)d_in[10];
    const float* Wl_pg = (const float*)d_in[11];
    const float* bl_pg = (const float*)d_in[12];
    const float* Wr_pg = (const float*)d_in[13];
    const float* Wl_gp = (const float*)d_in[14];
    const float* bl_gp = (const float*)d_in[15];
    const float* Wr_gp = (const float*)d_in[16];
    const float* Wl_ps = (const float*)d_in[17];
    const float* bl_ps = (const float*)d_in[18];
    const float* Wr_ps = (const float*)d_in[19];
    const float* Wl_sp = (const float*)d_in[20];
    const float* bl_sp = (const float*)d_in[21];
    const float* Wr_sp = (const float*)d_in[22];
    const float* W_gw  = (const float*)d_in[23];
    const float* b_gw  = (const float*)d_in[24];
    const float* W_sw  = (const float*)d_in[25];
    const float* b_sw  = (const float*)d_in[26];

    const int E_PG = in_sizes[3];
    const int E_GP = in_sizes[5];
    const int E_PS = in_sizes[7];
    const int E_SP = in_sizes[9];

    float* out = (float*)d_out;
    float* out_hpf = out;                       // [20000, 128]
    float* out_gw  = out + (size_t)NPF * D;     // [100000]
    float* out_sw  = out_gw + NGW;              // [30000]

    static float *mean_gw = nullptr, *mean_sw = nullptr, *mean_gp = nullptr, *mean_sp = nullptr;
    static float *wr_comb = nullptr;
    static int *cnt = nullptr, *rowptr = nullptr, *cursor = nullptr, *perm = nullptr, *partials = nullptr;
    static cudaStream_t s1 = nullptr, s2 = nullptr;
    static cudaEvent_t evRoot = nullptr, ev1 = nullptr, ev2 = nullptr, evP = nullptr;
    if (!mean_gw) {
        cudaGetSymbolAddress((void**)&mean_gw, g_mean_gw);
        cudaGetSymbolAddress((void**)&mean_sw, g_mean_sw);
        cudaGetSymbolAddress((void**)&mean_gp, g_mean_gp);
        cudaGetSymbolAddress((void**)&mean_sp, g_mean_sp);
        cudaGetSymbolAddress((void**)&wr_comb, g_wr_comb);
        cudaGetSymbolAddress((void**)&cnt, g_cnt);
        cudaGetSymbolAddress((void**)&rowptr, g_rowptr);
        cudaGetSymbolAddress((void**)&cursor, g_cursor);
        cudaGetSymbolAddress((void**)&perm, g_perm);
        cudaGetSymbolAddress((void**)&partials, g_partials);
        cudaStreamCreateWithFlags(&s1, cudaStreamNonBlocking);
        cudaStreamCreateWithFlags(&s2, cudaStreamNonBlocking);
        cudaEventCreateWithFlags(&evRoot, cudaEventDisableTiming);
        cudaEventCreateWithFlags(&ev1, cudaEventDisableTiming);
        cudaEventCreateWithFlags(&ev2, cudaEventDisableTiming);
        cudaEventCreateWithFlags(&evP, cudaEventDisableTiming);
    }

    const int off_pg = 0;
    const int off_gp = NGW;
    const int off_ps = NGW + NPF;
    const int off_sp = NGW + NPF + NSW;
    const int poff_pg = 0;
    const int poff_gp = E_PG;
    const int poff_ps = E_PG + E_GP;
    const int poff_sp = E_PG + E_GP + E_PS;

    // ---- root: zero all counters on the origin (capture) stream ----
    zero_int_kernel<<<(NTOT / 4 + 255) / 256, 256>>>(cnt, NTOT / 4);
    cudaEventRecord(evRoot, 0);
    cudaStreamWaitEvent(s1, evRoot, 0);
    cudaStreamWaitEvent(s2, evRoot, 0);

    // ================= Branch 1 (stream s1): gw head chain (largest) ========
    {
        hist_kernel<<<(E_PG + 255) / 256, 256, 0, s1>>>(ei_pg_dst, cnt + off_pg, E_PG);
        int nb = (NGW + 1023) / 1024;
        scan_reduce_kernel<<<nb, 256, 0, s1>>>(cnt + off_pg, NGW, partials + 0 * 128);
        scan_partials_kernel<<<1, 128, 0, s1>>>(partials + 0 * 128, nb);
        scan_write_kernel<<<nb, 256, 0, s1>>>(cnt + off_pg, NGW, partials + 0 * 128,
                                              rowptr + off_pg, cursor + off_pg);
        permute_kernel<<<(E_PG + 255) / 256, 256, 0, s1>>>(
            ei_pg_src, ei_pg_dst, cursor + off_pg, perm + poff_pg, E_PG);
        aggregate_kernel<<<(NGW + 7) / 8, 256, 0, s1>>>(
            x_pfas, rowptr + off_pg, perm + poff_pg, mean_gw, NGW, E_PG);
        gemm_fused<2, 1><<<(NGW + 127) / 128, 256, 0, s1>>>(
            mean_gw, x_gw, nullptr,
            Wl_pg, Wr_pg, nullptr,
            bl_pg, nullptr, W_gw, b_gw,
            out_gw, NGW);
    }

    // ================= Branch 2 (stream s2): sw head chain ==================
    {
        hist_kernel<<<(E_PS + 255) / 256, 256, 0, s2>>>(ei_ps_dst, cnt + off_ps, E_PS);
        int nb = (NSW + 1023) / 1024;
        scan_reduce_kernel<<<nb, 256, 0, s2>>>(cnt + off_ps, NSW, partials + 2 * 128);
        scan_partials_kernel<<<1, 128, 0, s2>>>(partials + 2 * 128, nb);
        scan_write_kernel<<<nb, 256, 0, s2>>>(cnt + off_ps, NSW, partials + 2 * 128,
                                              rowptr + off_ps, cursor + off_ps);
        permute_kernel<<<(E_PS + 255) / 256, 256, 0, s2>>>(
            ei_ps_src, ei_ps_dst, cursor + off_ps, perm + poff_ps, E_PS);
        aggregate_kernel<<<(NSW + 7) / 8, 256, 0, s2>>>(
            x_pfas, rowptr + off_ps, perm + poff_ps, mean_sw, NSW, E_PS);
        gemm_fused<2, 1><<<(NSW + 127) / 128, 256, 0, s2>>>(
            mean_sw, x_sw, nullptr,
            Wl_ps, Wr_ps, nullptr,
            bl_ps, nullptr, W_sw, b_sw,
            out_sw, NSW);
    }

    // ================= Branch 0 (origin stream): pfas CSR + aggs ============
    {
        addw_kernel<<<(D * D + 255) / 256, 256>>>(Wr_gp, Wr_sp, wr_comb);
        hist_kernel<<<(E_GP + 255) / 256, 256>>>(ei_gp_dst, cnt + off_gp, E_GP);
        hist_kernel<<<(E_SP + 255) / 256, 256>>>(ei_sp_dst, cnt + off_sp, E_SP);
        int nb = (NPF + 1023) / 1024;
        scan_reduce_kernel<<<nb, 256>>>(cnt + off_gp, NPF, partials + 1 * 128);
        scan_partials_kernel<<<1, 128>>>(partials + 1 * 128, nb);
        scan_write_kernel<<<nb, 256>>>(cnt + off_gp, NPF, partials + 1 * 128,
                                       rowptr + off_gp, cursor + off_gp);
        scan_reduce_kernel<<<nb, 256>>>(cnt + off_sp, NPF, partials + 3 * 128);
        scan_partials_kernel<<<1, 128>>>(partials + 3 * 128, nb);
        scan_write_kernel<<<nb, 256>>>(cnt + off_sp, NPF, partials + 3 * 128,
                                       rowptr + off_sp, cursor + off_sp);
        permute_kernel<<<(E_GP + 255) / 256, 256>>>(
            ei_gp_src, ei_gp_dst, cursor + off_gp, perm + poff_gp, E_GP);
        aggregate_kernel<<<(NPF + 7) / 8, 256>>>(
            x_gw, rowptr + off_gp, perm + poff_gp, mean_gp, NPF, E_GP);
        permute_kernel<<<(E_SP + 255) / 256, 256>>>(
            ei_sp_src, ei_sp_dst, cursor + off_sp, perm + poff_sp, E_SP);
        aggregate_kernel<<<(NPF + 7) / 8, 256>>>(
            x_sw, rowptr + off_sp, perm + poff_sp, mean_sp, NPF, E_SP);
        cudaEventRecord(evP, 0);
    }

    // pfas GEMM rebalanced onto s2 (shortest chain), gated on origin's aggs
    {
        cudaStreamWaitEvent(s2, evP, 0);
        gemm_fused<3, 0><<<(NPF + 127) / 128, 256, 0, s2>>>(
            mean_gp, mean_sp, x_pfas,
            Wl_gp, Wl_sp, wr_comb,
            bl_gp, bl_sp, nullptr, nullptr,
            out_hpf, NPF);
    }

    // ---- join branches back to the origin stream ----
    cudaEventRecord(ev1, s1);
    cudaEventRecord(ev2, s2);
    cudaStreamWaitEvent(0, ev1, 0);
    cudaStreamWaitEvent(0, ev2, 0);

    (void)n_in; (void)out_size;
}

// round 17
// speedup vs baseline: 1.0616x; 1.0616x over previous
#include <cuda_runtime.h>
#include <cuda_bf16.h>
#include <cstdint>

// ---------------------------------------------------------------------------
// Problem constants
// ---------------------------------------------------------------------------
#define NPF 20000
#define NGW 100000
#define NSW 30000
#define D   128

#define EPG 1600000
#define EGP 640000
#define EPS 480000
#define ESP 320000
#define ETOT (EPG + EGP + EPS + ESP)

#define NTOT (NGW + NPF + NSW + NPF)

// ---------------------------------------------------------------------------
// Device scratch (no allocations allowed -> __device__ globals)
// ---------------------------------------------------------------------------
__device__ float g_mean_gw[(size_t)NGW * D];
__device__ float g_mean_sw[(size_t)NSW * D];
__device__ float g_mean_gp[(size_t)NPF * D];
__device__ float g_mean_sp[(size_t)NPF * D];
__device__ int   g_cnt[NTOT];
__device__ int   g_rowptr[NTOT];
__device__ int   g_cursor[NTOT];
__device__ int   g_perm[ETOT];
__device__ int   g_partials[4 * 128];
__device__ float g_wr_comb[D * D];

// ---------------------------------------------------------------------------
// small utility kernels
// ---------------------------------------------------------------------------
__global__ void zero_int_kernel(int* __restrict__ p, int n4) {
    int i = blockIdx.x * blockDim.x + threadIdx.x;
    if (i < n4) reinterpret_cast<int4*>(p)[i] = make_int4(0, 0, 0, 0);
}

__global__ void addw_kernel(const float* __restrict__ a, const float* __restrict__ b,
                            float* __restrict__ o) {
    int i = blockIdx.x * blockDim.x + threadIdx.x;
    if (i < D * D) o[i] = a[i] + b[i];
}

// ---------------------------------------------------------------------------
// CSR build: histogram -> scan -> permutation (per relation)
// ---------------------------------------------------------------------------
__global__ void hist_kernel(const int* __restrict__ dst, int* __restrict__ cnt, int E) {
    int e = blockIdx.x * blockDim.x + threadIdx.x;
    if (e < E) atomicAdd(&cnt[dst[e]], 1);
}

// merged histogram over two edge lists (gp + sp)
__global__ void hist2_kernel(const int* __restrict__ d0, int off0, int E0,
                             const int* __restrict__ d1, int off1, int E1,
                             int* __restrict__ cnt) {
    int e = blockIdx.x * blockDim.x + threadIdx.x;
    if (e < E0)            atomicAdd(&cnt[off0 + d0[e]], 1);
    else if (e < E0 + E1)  atomicAdd(&cnt[off1 + d1[e - E0]], 1);
}

__global__ void scan_reduce_kernel(const int* __restrict__ cnt, int n,
                                   int* __restrict__ partials) {
    __shared__ int s[256];
    int t = threadIdx.x;
    int base = blockIdx.x * 1024 + t * 4;
    int sum = 0;
#pragma unroll
    for (int j = 0; j < 4; j++) {
        int idx = base + j;
        if (idx < n) sum += cnt[idx];
    }
    s[t] = sum;
    __syncthreads();
    for (int off = 128; off > 0; off >>= 1) {
        if (t < off) s[t] += s[t + off];
        __syncthreads();
    }
    if (t == 0) partials[blockIdx.x] = s[0];
}

// grid.y = which of two equal-size relations (gp / sp)
__global__ void scan_reduce2_kernel(const int* __restrict__ cnt, int off0, int off1,
                                    int n, int* __restrict__ p0, int* __restrict__ p1) {
    const int* c = cnt + (blockIdx.y ? off1 : off0);
    int* partials = blockIdx.y ? p1 : p0;
    __shared__ int s[256];
    int t = threadIdx.x;
    int base = blockIdx.x * 1024 + t * 4;
    int sum = 0;
#pragma unroll
    for (int j = 0; j < 4; j++) {
        int idx = base + j;
        if (idx < n) sum += c[idx];
    }
    s[t] = sum;
    __syncthreads();
    for (int off = 128; off > 0; off >>= 1) {
        if (t < off) s[t] += s[t + off];
        __syncthreads();
    }
    if (t == 0) partials[blockIdx.x] = s[0];
}

// parallel exclusive scan of <=128 partials; grid.x = #partial arrays
__global__ void scan_partials_kernel(int* __restrict__ partials, int nb) {
    __shared__ int s[128];
    int t = threadIdx.x;
    int* p = partials + blockIdx.x * 128;
    int v = (t < nb) ? p[t] : 0;
    s[t] = v;
    __syncthreads();
    for (int off = 1; off < 128; off <<= 1) {
        int y = (t >= off) ? s[t - off] : 0;
        __syncthreads();
        s[t] += y;
        __syncthreads();
    }
    if (t < nb) p[t] = s[t] - v;
}

__device__ __forceinline__ void scan_write_body(
    const int* __restrict__ c, int n, const int* __restrict__ partials,
    int* __restrict__ rp, int* __restrict__ cu)
{
    __shared__ int wsum[8];
    __shared__ int woff[8];
    int t = threadIdx.x;
    int lane = t & 31, warp = t >> 5;
    int base = blockIdx.x * 1024 + t * 4;
    int v[4];
    int tsum = 0;
#pragma unroll
    for (int j = 0; j < 4; j++) {
        int idx = base + j;
        v[j] = (idx < n) ? c[idx] : 0;
        tsum += v[j];
    }
    int incl = tsum;
#pragma unroll
    for (int o = 1; o < 32; o <<= 1) {
        int y = __shfl_up_sync(0xffffffffu, incl, o);
        if (lane >= o) incl += y;
    }
    int excl = incl - tsum;
    if (lane == 31) wsum[warp] = incl;
    __syncthreads();
    if (t == 0) {
        int r = 0;
        for (int i = 0; i < 8; i++) { woff[i] = r; r += wsum[i]; }
    }
    __syncthreads();
    int run = partials[blockIdx.x] + woff[warp] + excl;
#pragma unroll
    for (int j = 0; j < 4; j++) {
        int idx = base + j;
        if (idx < n) { rp[idx] = run; cu[idx] = run; run += v[j]; }
    }
}

__global__ void scan_write_kernel(const int* __restrict__ cnt, int n,
                                  const int* __restrict__ partials,
                                  int* __restrict__ rowptr,
                                  int* __restrict__ cursor) {
    scan_write_body(cnt, n, partials, rowptr, cursor);
}

// grid.y = which of two equal-size relations (gp / sp)
__global__ void scan_write2_kernel(const int* __restrict__ cnt, int off0, int off1,
                                   int n,
                                   const int* __restrict__ p0, const int* __restrict__ p1,
                                   int* __restrict__ rowptr, int* __restrict__ cursor) {
    int off = blockIdx.y ? off1 : off0;
    scan_write_body(cnt + off, n, blockIdx.y ? p1 : p0, rowptr + off, cursor + off);
}

__global__ void permute_kernel(const int* __restrict__ src, const int* __restrict__ dst,
                               int* __restrict__ cursor, int* __restrict__ perm, int E) {
    int e = blockIdx.x * blockDim.x + threadIdx.x;
    if (e < E) {
        int pos = atomicAdd(&cursor[dst[e]], 1);
        perm[pos] = src[e];
    }
}

// merged permute over two edge lists
__global__ void permute2_kernel(
    const int* __restrict__ s0, const int* __restrict__ d0, int off0, int poff0, int E0,
    const int* __restrict__ s1, const int* __restrict__ d1, int off1, int poff1, int E1,
    int* __restrict__ cursor, int* __restrict__ perm) {
    int e = blockIdx.x * blockDim.x + threadIdx.x;
    if (e < E0) {
        int pos = atomicAdd(&cursor[off0 + d0[e]], 1);
        perm[poff0 + pos] = s0[e];
    } else if (e < E0 + E1) {
        int le = e - E0;
        int pos = atomicAdd(&cursor[off1 + d1[le]], 1);
        perm[poff1 + pos] = s1[le];
    }
}

// ---------------------------------------------------------------------------
// Pull aggregation (fp32, R15-proven): one warp per node, 4-edge batching.
// ---------------------------------------------------------------------------
__device__ __forceinline__ void agg_body(
    const float* __restrict__ x,
    const int* __restrict__ rowptr, const int* __restrict__ perm,
    float* __restrict__ outmean, int w, int lane, int N, int E)
{
    int start = rowptr[w];
    int end   = (w + 1 < N) ? rowptr[w + 1] : E;

    float4 acc = make_float4(0.f, 0.f, 0.f, 0.f);
    for (int e0 = start; e0 < end; e0 += 32) {
        int idx = (e0 + lane < end) ? perm[e0 + lane] : 0;
        int m = min(32, end - e0);
        int j = 0;
        for (; j + 4 <= m; j += 4) {
            int s0 = __shfl_sync(0xffffffffu, idx, j + 0);
            int s1 = __shfl_sync(0xffffffffu, idx, j + 1);
            int s2 = __shfl_sync(0xffffffffu, idx, j + 2);
            int s3 = __shfl_sync(0xffffffffu, idx, j + 3);
            float4 v0 = *reinterpret_cast<const float4*>(x + (size_t)s0 * D + lane * 4);
            float4 v1 = *reinterpret_cast<const float4*>(x + (size_t)s1 * D + lane * 4);
            float4 v2 = *reinterpret_cast<const float4*>(x + (size_t)s2 * D + lane * 4);
            float4 v3 = *reinterpret_cast<const float4*>(x + (size_t)s3 * D + lane * 4);
            acc.x += (v0.x + v1.x) + (v2.x + v3.x);
            acc.y += (v0.y + v1.y) + (v2.y + v3.y);
            acc.z += (v0.z + v1.z) + (v2.z + v3.z);
            acc.w += (v0.w + v1.w) + (v2.w + v3.w);
        }
        for (; j < m; j++) {
            int s = __shfl_sync(0xffffffffu, idx, j);
            float4 v = *reinterpret_cast<const float4*>(x + (size_t)s * D + lane * 4);
            acc.x += v.x; acc.y += v.y; acc.z += v.z; acc.w += v.w;
        }
    }
    float inv = 1.0f / fmaxf((float)(end - start), 1.0f);
    acc.x *= inv; acc.y *= inv; acc.z *= inv; acc.w *= inv;
    *reinterpret_cast<float4*>(outmean + (size_t)w * D + lane * 4) = acc;
}

__global__ __launch_bounds__(256) void aggregate_kernel(
    const float* __restrict__ x,
    const int*   __restrict__ rowptr,
    const int*   __restrict__ perm,
    float* __restrict__ outmean,
    int N, int E)
{
    int w = (blockIdx.x * blockDim.x + threadIdx.x) >> 5;
    int lane = threadIdx.x & 31;
    if (w >= N) return;
    agg_body(x, rowptr, perm, outmean, w, lane, N, E);
}

// merged dual aggregation (gp + sp, both N=NPF)
__global__ __launch_bounds__(256) void aggregate2_kernel(
    const float* __restrict__ x0, const float* __restrict__ x1,
    const int* __restrict__ rowptr, int off0, int off1,
    const int* __restrict__ perm, int poff0, int poff1,
    float* __restrict__ m0, float* __restrict__ m1,
    int N, int E0, int E1)
{
    int w = (blockIdx.x * blockDim.x + threadIdx.x) >> 5;
    int lane = threadIdx.x & 31;
    if (w < N)
        agg_body(x0, rowptr + off0, perm + poff0, m0, w, lane, N, E0);
    else if (w < 2 * N)
        agg_body(x1, rowptr + off1, perm + poff1, m1, w - N, lane, N, E1);
}

// ---------------------------------------------------------------------------
// Fused GEMM, f32x2 packed, double-buffered (R15 proven):
//   h[row, :] = sum_seg A_seg[row, :] @ W_seg + bias1 (+ bias2)
//   MODE 0: out[row*128 + c] = relu(h)
//   MODE 1: out[row] = relu(h) . whead + bhead
// ---------------------------------------------------------------------------
template<int NSEG, int MODE>
__global__ __launch_bounds__(256) void gemm_fused(
    const float* __restrict__ A0, const float* __restrict__ A1,
    const float* __restrict__ A2,
    const float* __restrict__ W0, const float* __restrict__ W1,
    const float* __restrict__ W2,
    const float* __restrict__ bias1, const float* __restrict__ bias2,
    const float* __restrict__ whead, const float* __restrict__ bhead,
    float* __restrict__ out, int n_rows)
{
    constexpr int KC  = 16;
    constexpr int LDT = 132;
    __shared__ float As[2][KC][LDT];
    __shared__ float Ws[2][KC][LDT];
    __shared__ float red[128];

    const int t    = threadIdx.x;
    const int row0 = blockIdx.x * 128;
    const int trow = t >> 4;
    const int tcol = t & 15;

    const float* Aseg[3] = {A0, A1, A2};
    const float* Wseg[3] = {W0, W1, W2};

    const int a_row = t >> 1;
    const int a_q   = (t & 1) * 2;
    const int w_kk  = t >> 4;
    const int w_cq  = t & 15;

    unsigned long long accp[8][4];
#pragma unroll
    for (int i = 0; i < 8; i++)
#pragma unroll
        for (int j2 = 0; j2 < 4; j2++) accp[i][j2] = 0ull;

    const int nchunks = NSEG * D / KC;

    float4 pa0, pa1, pw0, pw1;

    auto prefetch = [&](int ch) {
        const int k0   = ch * KC;
        const int seg  = k0 / D;
        const int kin0 = k0 % D;
        const float* A = Aseg[seg];
        const float* W = Wseg[seg];
        int grow = row0 + a_row;
        if (grow < n_rows) {
            pa0 = *reinterpret_cast<const float4*>(A + (size_t)grow * D + kin0 + a_q * 4);
            pa1 = *reinterpret_cast<const float4*>(A + (size_t)grow * D + kin0 + (a_q + 1) * 4);
        } else {
            pa0 = make_float4(0.f, 0.f, 0.f, 0.f);
            pa1 = make_float4(0.f, 0.f, 0.f, 0.f);
        }
        pw0 = *reinterpret_cast<const float4*>(W + (size_t)(kin0 + w_kk) * D + w_cq * 4);
        pw1 = *reinterpret_cast<const float4*>(W + (size_t)(kin0 + w_kk) * D + (w_cq + 16) * 4);
    };

    auto store_stage = [&](int b) {
        As[b][a_q * 4 + 0][a_row] = pa0.x;
        As[b][a_q * 4 + 1][a_row] = pa0.y;
        As[b][a_q * 4 + 2][a_row] = pa0.z;
        As[b][a_q * 4 + 3][a_row] = pa0.w;
        As[b][a_q * 4 + 4][a_row] = pa1.x;
        As[b][a_q * 4 + 5][a_row] = pa1.y;
        As[b][a_q * 4 + 6][a_row] = pa1.z;
        As[b][a_q * 4 + 7][a_row] = pa1.w;
        *reinterpret_cast<float4*>(&Ws[b][w_kk][w_cq * 4]) = pw0;
        *reinterpret_cast<float4*>(&Ws[b][w_kk][(w_cq + 16) * 4]) = pw1;
    };

    prefetch(0);

    for (int ch = 0; ch < nchunks; ch++) {
        const int b = ch & 1;
        store_stage(b);
        __syncthreads();
        if (ch + 1 < nchunks) prefetch(ch + 1);

#pragma unroll
        for (int kk = 0; kk < KC; kk++) {
            float4 a0 = *reinterpret_cast<const float4*>(&As[b][kk][trow * 4]);
            float4 a1 = *reinterpret_cast<const float4*>(&As[b][kk][64 + trow * 4]);
            unsigned long long wp[4];
            wp[0] = *reinterpret_cast<const unsigned long long*>(&Ws[b][kk][tcol * 4]);
            wp[1] = *reinterpret_cast<const unsigned long long*>(&Ws[b][kk][tcol * 4 + 2]);
            wp[2] = *reinterpret_cast<const unsigned long long*>(&Ws[b][kk][64 + tcol * 4]);
            wp[3] = *reinterpret_cast<const unsigned long long*>(&Ws[b][kk][64 + tcol * 4 + 2]);
            float a[8] = {a0.x, a0.y, a0.z, a0.w, a1.x, a1.y, a1.z, a1.w};
#pragma unroll
            for (int i = 0; i < 8; i++) {
                unsigned long long ap;
                asm("mov.b64 %0, {%1, %1};" : "=l"(ap) : "f"(a[i]));
#pragma unroll
                for (int j2 = 0; j2 < 4; j2++)
                    asm("fma.rn.f32x2 %0, %1, %2, %0;"
                        : "+l"(accp[i][j2]) : "l"(ap), "l"(wp[j2]));
            }
        }
    }

    float acc[8][8];
#pragma unroll
    for (int i = 0; i < 8; i++)
#pragma unroll
        for (int j2 = 0; j2 < 4; j2++)
            asm("mov.b64 {%0, %1}, %2;"
                : "=f"(acc[i][2 * j2]), "=f"(acc[i][2 * j2 + 1]) : "l"(accp[i][j2]));

    int cidx[8], ridx[8];
#pragma unroll
    for (int j = 0; j < 8; j++)
        cidx[j] = (j < 4) ? (tcol * 4 + j) : (64 + tcol * 4 + (j - 4));
#pragma unroll
    for (int i = 0; i < 8; i++)
        ridx[i] = (i < 4) ? (trow * 4 + i) : (64 + trow * 4 + (i - 4));

    float b[8];
#pragma unroll
    for (int j = 0; j < 8; j++)
        b[j] = bias1[cidx[j]] + (bias2 ? bias2[cidx[j]] : 0.f);

    if (MODE == 0) {
#pragma unroll
        for (int i = 0; i < 8; i++) {
            int grow = row0 + ridx[i];
            if (grow < n_rows) {
#pragma unroll
                for (int j = 0; j < 8; j++)
                    out[(size_t)grow * D + cidx[j]] = fmaxf(acc[i][j] + b[j], 0.f);
            }
        }
    } else {
        float wh[8];
#pragma unroll
        for (int j = 0; j < 8; j++) wh[j] = whead[cidx[j]];
        __syncthreads();
        if (t < 128) red[t] = 0.f;
        __syncthreads();
#pragma unroll
        for (int i = 0; i < 8; i++) {
            float partial = 0.f;
#pragma unroll
            for (int j = 0; j < 8; j++)
                partial += fmaxf(acc[i][j] + b[j], 0.f) * wh[j];
            atomicAdd(&red[ridx[i]], partial);
        }
        __syncthreads();
        if (t < 128) {
            int grow = row0 + t;
            if (grow < n_rows) out[grow] = red[t] + bhead[0];
        }
    }
}

// ---------------------------------------------------------------------------
// Launch: R15's proven 3-branch fork (2 extra streams + 3 events), with the
// origin chain's launch count reduced via merged kernels.
// ---------------------------------------------------------------------------
extern "C" void kernel_launch(void* const* d_in, const int* in_sizes, int n_in,
                              void* d_out, int out_size)
{
    const float* x_pfas = (const float*)d_in[0];
    const float* x_gw   = (const float*)d_in[1];
    const float* x_sw   = (const float*)d_in[2];
    const int* ei_pg_src = (const int*)d_in[3];
    const int* ei_pg_dst = (const int*)d_in[4];
    const int* ei_gp_src = (const int*)d_in[5];
    const int* ei_gp_dst = (const int*)d_in[6];
    const int* ei_ps_src = (const int*)d_in[7];
    const int* ei_ps_dst = (const int*)d_in[8];
    const int* ei_sp_src = (const int*)d_in[9];
    const int* ei_sp_dst = (const int*)d_in[10];
    const float* Wl_pg = (const float*)d_in[11];
    const float* bl_pg = (const float*)d_in[12];
    const float* Wr_pg = (const float*)d_in[13];
    const float* Wl_gp = (const float*)d_in[14];
    const float* bl_gp = (const float*)d_in[15];
    const float* Wr_gp = (const float*)d_in[16];
    const float* Wl_ps = (const float*)d_in[17];
    const float* bl_ps = (const float*)d_in[18];
    const float* Wr_ps = (const float*)d_in[19];
    const float* Wl_sp = (const float*)d_in[20];
    const float* bl_sp = (const float*)d_in[21];
    const float* Wr_sp = (const float*)d_in[22];
    const float* W_gw  = (const float*)d_in[23];
    const float* b_gw  = (const float*)d_in[24];
    const float* W_sw  = (const float*)d_in[25];
    const float* b_sw  = (const float*)d_in[26];

    const int E_PG = in_sizes[3];
    const int E_GP = in_sizes[5];
    const int E_PS = in_sizes[7];
    const int E_SP = in_sizes[9];

    float* out = (float*)d_out;
    float* out_hpf = out;                       // [20000, 128]
    float* out_gw  = out + (size_t)NPF * D;     // [100000]
    float* out_sw  = out_gw + NGW;              // [30000]

    static float *mean_gw = nullptr, *mean_sw = nullptr, *mean_gp = nullptr, *mean_sp = nullptr;
    static float *wr_comb = nullptr;
    static int *cnt = nullptr, *rowptr = nullptr, *cursor = nullptr, *perm = nullptr, *partials = nullptr;
    static cudaStream_t s1 = nullptr, s2 = nullptr;
    static cudaEvent_t evRoot = nullptr, ev1 = nullptr, ev2 = nullptr;
    if (!mean_gw) {
        cudaGetSymbolAddress((void**)&mean_gw, g_mean_gw);
        cudaGetSymbolAddress((void**)&mean_sw, g_mean_sw);
        cudaGetSymbolAddress((void**)&mean_gp, g_mean_gp);
        cudaGetSymbolAddress((void**)&mean_sp, g_mean_sp);
        cudaGetSymbolAddress((void**)&wr_comb, g_wr_comb);
        cudaGetSymbolAddress((void**)&cnt, g_cnt);
        cudaGetSymbolAddress((void**)&rowptr, g_rowptr);
        cudaGetSymbolAddress((void**)&cursor, g_cursor);
        cudaGetSymbolAddress((void**)&perm, g_perm);
        cudaGetSymbolAddress((void**)&partials, g_partials);
        cudaStreamCreateWithFlags(&s1, cudaStreamNonBlocking);
        cudaStreamCreateWithFlags(&s2, cudaStreamNonBlocking);
        cudaEventCreateWithFlags(&evRoot, cudaEventDisableTiming);
        cudaEventCreateWithFlags(&ev1, cudaEventDisableTiming);
        cudaEventCreateWithFlags(&ev2, cudaEventDisableTiming);
    }

    const int off_pg = 0;
    const int off_gp = NGW;
    const int off_ps = NGW + NPF;
    const int off_sp = NGW + NPF + NSW;
    const int poff_pg = 0;
    const int poff_gp = E_PG;
    const int poff_ps = E_PG + E_GP;
    const int poff_sp = E_PG + E_GP + E_PS;

    // ---- root: zero all counters on the origin (capture) stream ----
    zero_int_kernel<<<(NTOT / 4 + 255) / 256, 256>>>(cnt, NTOT / 4);
    cudaEventRecord(evRoot, 0);
    cudaStreamWaitEvent(s1, evRoot, 0);
    cudaStreamWaitEvent(s2, evRoot, 0);

    // ================= Branch 1 (stream s1): gw head chain (largest) ========
    {
        hist_kernel<<<(E_PG + 255) / 256, 256, 0, s1>>>(ei_pg_dst, cnt + off_pg, E_PG);
        int nb = (NGW + 1023) / 1024;
        scan_reduce_kernel<<<nb, 256, 0, s1>>>(cnt + off_pg, NGW, partials + 0 * 128);
        scan_partials_kernel<<<1, 128, 0, s1>>>(partials + 0 * 128, nb);
        scan_write_kernel<<<nb, 256, 0, s1>>>(cnt + off_pg, NGW, partials + 0 * 128,
                                              rowptr + off_pg, cursor + off_pg);
        permute_kernel<<<(E_PG + 255) / 256, 256, 0, s1>>>(
            ei_pg_src, ei_pg_dst, cursor + off_pg, perm + poff_pg, E_PG);
        aggregate_kernel<<<(NGW + 7) / 8, 256, 0, s1>>>(
            x_pfas, rowptr + off_pg, perm + poff_pg, mean_gw, NGW, E_PG);
        gemm_fused<2, 1><<<(NGW + 127) / 128, 256, 0, s1>>>(
            mean_gw, x_gw, nullptr,
            Wl_pg, Wr_pg, nullptr,
            bl_pg, nullptr, W_gw, b_gw,
            out_gw, NGW);
    }

    // ================= Branch 2 (stream s2): sw head chain ==================
    {
        hist_kernel<<<(E_PS + 255) / 256, 256, 0, s2>>>(ei_ps_dst, cnt + off_ps, E_PS);
        int nb = (NSW + 1023) / 1024;
        scan_reduce_kernel<<<nb, 256, 0, s2>>>(cnt + off_ps, NSW, partials + 2 * 128);
        scan_partials_kernel<<<1, 128, 0, s2>>>(partials + 2 * 128, nb);
        scan_write_kernel<<<nb, 256, 0, s2>>>(cnt + off_ps, NSW, partials + 2 * 128,
                                              rowptr + off_ps, cursor + off_ps);
        permute_kernel<<<(E_PS + 255) / 256, 256, 0, s2>>>(
            ei_ps_src, ei_ps_dst, cursor + off_ps, perm + poff_ps, E_PS);
        aggregate_kernel<<<(NSW + 7) / 8, 256, 0, s2>>>(
            x_pfas, rowptr + off_ps, perm + poff_ps, mean_sw, NSW, E_PS);
        gemm_fused<2, 1><<<(NSW + 127) / 128, 256, 0, s2>>>(
            mean_sw, x_sw, nullptr,
            Wl_ps, Wr_ps, nullptr,
            bl_ps, nullptr, W_sw, b_sw,
            out_sw, NSW);
    }

    // ================= Branch 0 (origin stream): pfas chain (merged) ========
    {
        addw_kernel<<<(D * D + 255) / 256, 256>>>(Wr_gp, Wr_sp, wr_comb);
        // merged histogram over gp + sp
        hist2_kernel<<<(E_GP + E_SP + 255) / 256, 256>>>(
            ei_gp_dst, off_gp, E_GP, ei_sp_dst, off_sp, E_SP, cnt);
        int nb = (NPF + 1023) / 1024;
        // merged scans (grid.y = relation)
        {
            dim3 g(nb, 2);
            scan_reduce2_kernel<<<g, 256>>>(cnt, off_gp, off_sp, NPF,
                                            partials + 1 * 128, partials + 3 * 128);
        }
        scan_partials_kernel<<<1, 128>>>(partials + 1 * 128, nb);
        scan_partials_kernel<<<1, 128>>>(partials + 3 * 128, nb);
        {
            dim3 g(nb, 2);
            scan_write2_kernel<<<g, 256>>>(cnt, off_gp, off_sp, NPF,
                                           partials + 1 * 128, partials + 3 * 128,
                                           rowptr, cursor);
        }
        // merged permute over gp + sp
        permute2_kernel<<<(E_GP + E_SP + 255) / 256, 256>>>(
            ei_gp_src, ei_gp_dst, off_gp, poff_gp, E_GP,
            ei_sp_src, ei_sp_dst, off_sp, poff_sp, E_SP,
            cursor, perm);
        // merged dual aggregation
        aggregate2_kernel<<<(2 * NPF + 7) / 8, 256>>>(
            x_gw, x_sw, rowptr, off_gp, off_sp, perm, poff_gp, poff_sp,
            mean_gp, mean_sp, NPF, E_GP, E_SP);
        gemm_fused<3, 0><<<(NPF + 127) / 128, 256>>>(
            mean_gp, mean_sp, x_pfas,
            Wl_gp, Wl_sp, wr_comb,
            bl_gp, bl_sp, nullptr, nullptr,
            out_hpf, NPF);
    }

    // ---- join branches back to the origin stream ----
    cudaEventRecord(ev1, s1);
    cudaEventRecord(ev2, s2);
    cudaStreamWaitEvent(0, ev1, 0);
    cudaStreamWaitEvent(0, ev2, 0);

    (void)n_in; (void)out_size;
}